// round 11
// baseline (speedup 1.0000x reference)
#include <cuda_runtime.h>
#include <cuda_bf16.h>
#include <math.h>
#include <stdint.h>

#define BATCH 4
#define TLEN  4096
#define DIM   768
#define NSEL  256
#define HID   200
#define NPAIR 32640
#define MTILE 64             // pairs per CTA (8x8 token block)
#define NB8   32             // token blocks per batch (256/8)
#define NBLK  528            // NB8*(NB8+1)/2
#define K2PAD 224            // padded K for layer 2 (7 chunks of 32)
#define XS_STRIDE 40         // bf16 elems per smem row (80B)
#define HS_STRIDE 232        // bf16 elems per Hs row (464B)
#define L1C   (DIM / 32)     // 24 chunks
#define L2C   (K2PAD / 32)   // 7 chunks
#define NTILES 25            // 200/8 n-tiles

// dynamic smem layout (bytes) — W/E are 3-slot rings for pipeline depth 2
#define XS0_OFF 0                      // 5120
#define XS1_OFF 5120                   // 5120
#define WS0_OFF 10240                  // 16000
#define WS1_OFF 26240                  // 16000
#define WS2_OFF 42240                  // 16000
#define ES0_OFF 58240                  // 2048 (16 rows x 32 fp32)
#define ES1_OFF 60288                  // 2048
#define ES2_OFF 62336                  // 2048
#define AB_OFF  64384                  // 12800 (16 rows x 200 fp32)
#define HS_OFF  77184                  // 29696
#define DYN_BYTES 106880

// ---------------- device scratch ----------------
__device__ float          g_E  [BATCH * NSEL * DIM];
__device__ float          g_AB [BATCH * NSEL * 2 * HID];
__device__ __nv_bfloat16  g_W1t[HID * DIM];             // [h][d]
__device__ __nv_bfloat16  g_W2t[HID * K2PAD];           // [h][k], k>=200 zero
__device__ float          g_S  [BATCH * NSEL * NSEL];

// ---------------- helpers ----------------
__device__ __forceinline__ void mma16816(float* c, const uint32_t* a, const uint32_t* b) {
    asm volatile(
        "mma.sync.aligned.m16n8k16.row.col.f32.bf16.bf16.f32 "
        "{%0,%1,%2,%3}, {%4,%5,%6,%7}, {%8,%9}, {%0,%1,%2,%3};"
        : "+f"(c[0]), "+f"(c[1]), "+f"(c[2]), "+f"(c[3])
        : "r"(a[0]), "r"(a[1]), "r"(a[2]), "r"(a[3]), "r"(b[0]), "r"(b[1]));
}
__device__ __forceinline__ void ldsm_x4(uint32_t* r, uint32_t addr) {
    asm volatile("ldmatrix.sync.aligned.m8n8.x4.shared.b16 {%0,%1,%2,%3}, [%4];"
                 : "=r"(r[0]), "=r"(r[1]), "=r"(r[2]), "=r"(r[3]) : "r"(addr));
}
__device__ __forceinline__ void ldsm_x2(uint32_t* r, uint32_t addr) {
    asm volatile("ldmatrix.sync.aligned.m8n8.x2.shared.b16 {%0,%1}, [%2];"
                 : "=r"(r[0]), "=r"(r[1]) : "r"(addr));
}
__device__ __forceinline__ void cpasync16(uint32_t smem_addr, const void* gsrc) {
    asm volatile("cp.async.cg.shared.global [%0], [%1], 16;"
                 :: "r"(smem_addr), "l"(gsrc) : "memory");
}
__device__ __forceinline__ void cpasync_commit() {
    asm volatile("cp.async.commit_group;" ::: "memory");
}
__device__ __forceinline__ void cpasync_wait0() {
    asm volatile("cp.async.wait_group 0;" ::: "memory");
}
__device__ __forceinline__ void cpasync_wait1() {
    asm volatile("cp.async.wait_group 1;" ::: "memory");
}

// ---------------- fused prep: gather + W1t + W2t ----------------
#define PREP_GATH  (BATCH * NSEL)                       // 1024
#define PREP_W1    ((HID * DIM + 255) / 256)            // 600
#define PREP_W2    ((HID * K2PAD + 255) / 256)          // 175
#define PREP_BLKS  (PREP_GATH + PREP_W1 + PREP_W2)

__global__ void k_prep(const float* __restrict__ emb, const int* __restrict__ idx,
                       const float* __restrict__ W1, const float* __restrict__ W2) {
    int blk = blockIdx.x;
    int tid = threadIdx.x;
    if (blk < PREP_GATH) {
        int b = blk / NSEL, n = blk % NSEL;
        int t = idx[b * NSEL + n];
        const float4* src = (const float4*)(emb + ((size_t)b * TLEN + t) * DIM);
        float4* dst = (float4*)(g_E + (size_t)blk * DIM);
        if (tid < DIM / 4) dst[tid] = src[tid];
        return;
    }
    blk -= PREP_GATH;
    if (blk < PREP_W1) {
        int e = blk * 256 + tid;
        if (e < HID * DIM) {
            int h = e / DIM, d = e % DIM;
            g_W1t[e] = __float2bfloat16(W1[(size_t)(2 * DIM + d) * HID + h]);
        }
        return;
    }
    blk -= PREP_W1;
    {
        int e = blk * 256 + tid;
        if (e < HID * K2PAD) {
            int h = e / K2PAD, k = e % K2PAD;
            float v = (k < HID) ? W2[(size_t)k * HID + h] : 0.f;
            g_W2t[e] = __float2bfloat16(v);
        }
    }
}

// ---------------- exact A/B partials (fp32 SIMT, small) ----------------
__global__ void k_ab(const float* __restrict__ W1) {
    __shared__ __align__(16) float As[16][64 + 4];
    __shared__ __align__(16) float Bs[16][64 + 4];
    int bm = blockIdx.x * 64, bn = blockIdx.y * 64;
    int tx = threadIdx.x % 16, ty = threadIdx.x / 16;
    float acc[4][4] = {};
    for (int k0 = 0; k0 < DIM; k0 += 16) {
        for (int t = threadIdx.x; t < 1024; t += 256) {
            int k = t % 16, m = t / 16;
            As[k][m] = g_E[(size_t)(bm + m) * DIM + k0 + k];
        }
        for (int t = threadIdx.x; t < 1024; t += 256) {
            int n = t % 64, k = t / 64;
            int c = bn + n;
            float v = 0.f;
            if (c < 2 * HID) {
                int half = c / HID, h = c - half * HID;
                v = W1[(size_t)(half * DIM + k0 + k) * HID + h];
            }
            Bs[k][n] = v;
        }
        __syncthreads();
        #pragma unroll
        for (int k = 0; k < 16; ++k) {
            float a[4], bb[4];
            #pragma unroll
            for (int u = 0; u < 4; ++u) a[u] = As[k][ty * 4 + u];
            #pragma unroll
            for (int v = 0; v < 4; ++v) bb[v] = Bs[k][tx * 4 + v];
            #pragma unroll
            for (int u = 0; u < 4; ++u)
                #pragma unroll
                for (int v = 0; v < 4; ++v)
                    acc[u][v] = fmaf(a[u], bb[v], acc[u][v]);
        }
        __syncthreads();
    }
    #pragma unroll
    for (int u = 0; u < 4; ++u)
        #pragma unroll
        for (int v = 0; v < 4; ++v) {
            int c = bn + tx * 4 + v;
            if (c < 2 * HID)
                g_AB[(size_t)(bm + ty * 4 + u) * (2 * HID) + c] = acc[u][v];
        }
}

// ================= fused MLP (pair-blocked, depth-2 cp.async pipeline) =================
__global__ __launch_bounds__(256, 2)
void k_fused(const float* __restrict__ b1, const float* __restrict__ b2,
             const float* __restrict__ W3, const float* __restrict__ b3) {
    extern __shared__ __align__(16) char dynsm[];
    uint32_t dynbase = (uint32_t)__cvta_generic_to_shared(dynsm);
    uint32_t xs_base[2] = { dynbase + XS0_OFF, dynbase + XS1_OFF };
    uint32_t ws_base[3] = { dynbase + WS0_OFF, dynbase + WS1_OFF, dynbase + WS2_OFF };
    uint32_t es_base[3] = { dynbase + ES0_OFF, dynbase + ES1_OFF, dynbase + ES2_OFF };
    uint32_t ab_base = dynbase + AB_OFF;
    uint32_t hs_base = dynbase + HS_OFF;
    __nv_bfloat16* XsBuf[2] = { (__nv_bfloat16*)(dynsm + XS0_OFF),
                                (__nv_bfloat16*)(dynsm + XS1_OFF) };
    float* EsBuf[3] = { (float*)(dynsm + ES0_OFF), (float*)(dynsm + ES1_OFF),
                        (float*)(dynsm + ES2_OFF) };
    float* sAB = (float*)(dynsm + AB_OFF);              // [16][200]
    __nv_bfloat16* Hs = (__nv_bfloat16*)(dynsm + HS_OFF);

    __shared__ float b1s[HID], b2s[HID], W3s[HID];
    __shared__ float sred[MTILE][4];

    int tid = threadIdx.x;
    int b = blockIdx.y;

    // decode token block (bi, bj), bi >= bj
    int tb = blockIdx.x;
    int bi = (int)((sqrtf(8.0f * (float)tb + 1.0f) - 1.0f) * 0.5f);
    while (bi * (bi + 1) / 2 > tb) --bi;
    while ((bi + 1) * (bi + 2) / 2 <= tb) ++bi;
    int bj = tb - bi * (bi + 1) / 2;

    if (tid < HID) { b1s[tid] = b1[tid]; b2s[tid] = b2[tid]; W3s[tid] = W3[tid]; }

    const float* Eb = g_E + (size_t)b * NSEL * DIM;
    int wid = tid / 32, lane = tid % 32;
    int wm = wid & 1, wn = wid >> 1;
    int q = lane >> 2, l4 = lane & 3;

    int rowA = wm * 32 + (lane & 15);          // + mt*16
    int colhA = (lane >> 4) * 8;
    int rowB = lane & 7;                       // + nt_g*8
    int colhB = ((lane >> 3) & 1) * 8;

    // E-chunk cp.async coords (tid < 128)
    int er = tid >> 3, eseg = tid & 7;
    int etok = (er < 8) ? (bi * 8 + er) : (bj * 8 + er - 8);
    const float* esrc_row = Eb + (size_t)etok * DIM + eseg * 4;
    uint32_t edst = (uint32_t)((er * 32 + eseg * 4) * 4);

    // X-build coords (4 u32 per thread)
    int xr[4], xk[4];
    #pragma unroll
    for (int u = 0; u < 4; ++u) {
        int e = tid + u * 256;
        xr[u] = e >> 4;
        xk[u] = (e & 15) * 2;
    }

    float acc[2][7][4];
    #pragma unroll
    for (int mt = 0; mt < 2; ++mt)
        #pragma unroll
        for (int t = 0; t < 7; ++t)
            #pragma unroll
            for (int v = 0; v < 4; ++v) acc[mt][t][v] = 0.f;

    // ---------------- prologue: group0 = {AB, E(0), W1(0)}, group1 = {E(1), W1(1)} ----------------
    {
        #pragma unroll
        for (int u = 0; u < 4; ++u) {
            int e = tid + u * 256;
            if (e < 800) {
                int row = e / 50, seg = e % 50;
                int tok = (row < 8) ? (bi * 8 + row) : (bj * 8 + row - 8);
                int foff = (row < 8) ? 0 : HID;
                cpasync16(ab_base + (row * HID + seg * 4) * 4,
                          g_AB + ((size_t)(b * NSEL + tok)) * (2 * HID) + foff + seg * 4);
            }
        }
        if (tid < 128)
            cpasync16(es_base[0] + edst, esrc_row);
        #pragma unroll
        for (int u = 0; u < 4; ++u) {
            int e = tid + u * 256;
            if (e < HID * 4) {
                int n = e >> 2, seg = e & 3;
                cpasync16(ws_base[0] + n * (XS_STRIDE * 2) + seg * 16,
                          g_W1t + (size_t)n * DIM + seg * 8);
            }
        }
        cpasync_commit();               // group 0
        if (tid < 128)
            cpasync16(es_base[1] + edst, esrc_row + 32);
        #pragma unroll
        for (int u = 0; u < 4; ++u) {
            int e = tid + u * 256;
            if (e < HID * 4) {
                int n = e >> 2, seg = e & 3;
                cpasync16(ws_base[1] + n * (XS_STRIDE * 2) + seg * 16,
                          g_W1t + (size_t)n * DIM + 32 + seg * 8);
            }
        }
        cpasync_commit();               // group 1
        cpasync_wait1();                // group 0 complete
        __syncthreads();
        // build X(0) from Es[0]
        #pragma unroll
        for (int u = 0; u < 4; ++u) {
            int ri = xr[u] >> 3, rj = xr[u] & 7;
            const float2 xi = *(const float2*)&EsBuf[0][ri * 32 + xk[u]];
            const float2 xj = *(const float2*)&EsBuf[0][(8 + rj) * 32 + xk[u]];
            __nv_bfloat162 v = __floats2bfloat162_rn(xi.x * xj.x, xi.y * xj.y);
            *(uint32_t*)&XsBuf[0][xr[u] * XS_STRIDE + xk[u]] = *(uint32_t*)&v;
        }
        __syncthreads();
    }

    // ---------------- layer-1 mainloop ----------------
    for (int c = 0; c < L1C; ++c) {
        uint32_t xsb = xs_base[c & 1];
        uint32_t wsb = ws_base[c % 3];
        bool more = (c + 1 < L1C);

        // issue fills for c+2 (2 iterations ahead)
        if (c + 2 < L1C) {
            int s2 = (c + 2) % 3;
            int c2 = (c + 2) * 32;
            if (tid < 128)
                cpasync16(es_base[s2] + edst, esrc_row + c2);
            #pragma unroll
            for (int u = 0; u < 4; ++u) {
                int e = tid + u * 256;
                if (e < HID * 4) {
                    int n = e >> 2, seg = e & 3;
                    cpasync16(ws_base[s2] + n * (XS_STRIDE * 2) + seg * 16,
                              g_W1t + (size_t)n * DIM + c2 + seg * 8);
                }
            }
        }
        cpasync_commit();

        // MMA(c)
        #pragma unroll
        for (int ks = 0; ks < 2; ++ks) {
            int kb = ks * 16;
            uint32_t a[2][4];
            #pragma unroll
            for (int mt = 0; mt < 2; ++mt)
                ldsm_x4(a[mt], xsb + ((rowA + mt * 16) * XS_STRIDE + kb + colhA) * 2);
            #pragma unroll
            for (int t = 0; t < 7; ++t) {
                int nt_g = wn + 4 * t;
                if (nt_g < NTILES) {
                    uint32_t bb[2];
                    ldsm_x2(bb, wsb + ((nt_g * 8 + rowB) * XS_STRIDE + kb + colhB) * 2);
                    #pragma unroll
                    for (int mt = 0; mt < 2; ++mt)
                        mma16816(acc[mt][t], a[mt], bb);
                }
            }
        }

        // wait for c+1 (leaves c+2 in flight), build X(c+1)
        if (more) {
            cpasync_wait1();
            int s1 = (c + 1) % 3;
            int nb = (c + 1) & 1;
            #pragma unroll
            for (int u = 0; u < 4; ++u) {
                int ri = xr[u] >> 3, rj = xr[u] & 7;
                const float2 xi = *(const float2*)&EsBuf[s1][ri * 32 + xk[u]];
                const float2 xj = *(const float2*)&EsBuf[s1][(8 + rj) * 32 + xk[u]];
                __nv_bfloat162 v = __floats2bfloat162_rn(xi.x * xj.x, xi.y * xj.y);
                *(uint32_t*)&XsBuf[nb][xr[u] * XS_STRIDE + xk[u]] = *(uint32_t*)&v;
            }
        }
        __syncthreads();
    }

    // ---------------- layer-1 epilogue -> Hs (AB from smem) ----------------
    #pragma unroll
    for (int mt = 0; mt < 2; ++mt) {
        #pragma unroll
        for (int half = 0; half < 2; ++half) {
            int r = wm * 32 + mt * 16 + q + 8 * half;
            int ri = r >> 3, rj = r & 7;
            #pragma unroll
            for (int t = 0; t < 7; ++t) {
                int nt_g = wn + 4 * t;
                if (nt_g < NTILES) {
                    int col = nt_g * 8 + 2 * l4;
                    float2 ai = *(const float2*)&sAB[ri * HID + col];
                    float2 bj = *(const float2*)&sAB[(8 + rj) * HID + col];
                    float v0 = acc[mt][t][half * 2 + 0] + ai.x + bj.x + b1s[col];
                    float v1 = acc[mt][t][half * 2 + 1] + ai.y + bj.y + b1s[col + 1];
                    __nv_bfloat162 o = __floats2bfloat162_rn(fmaxf(v0, 0.f), fmaxf(v1, 0.f));
                    *(uint32_t*)&Hs[r * HS_STRIDE + col] = *(uint32_t*)&o;
                }
            }
        }
    }
    // zero pad cols [200,224)
    for (int e = tid; e < MTILE * 12; e += 256) {
        int r = e / 12, cc = HID + (e % 12) * 2;
        *(uint32_t*)&Hs[r * HS_STRIDE + cc] = 0u;
    }

    #pragma unroll
    for (int mt = 0; mt < 2; ++mt)
        #pragma unroll
        for (int t = 0; t < 7; ++t)
            #pragma unroll
            for (int v = 0; v < 4; ++v) acc[mt][t][v] = 0.f;

    // ---------------- layer-2 prologue (drain, then groups for c=0,1) ----------------
    {
        cpasync_wait0();                // drain layer-1 leftovers
        #pragma unroll
        for (int u = 0; u < 4; ++u) {
            int e = tid + u * 256;
            if (e < HID * 4) {
                int n = e >> 2, seg = e & 3;
                cpasync16(ws_base[0] + n * (XS_STRIDE * 2) + seg * 16,
                          g_W2t + (size_t)n * K2PAD + seg * 8);
            }
        }
        cpasync_commit();               // group 0
        #pragma unroll
        for (int u = 0; u < 4; ++u) {
            int e = tid + u * 256;
            if (e < HID * 4) {
                int n = e >> 2, seg = e & 3;
                cpasync16(ws_base[1] + n * (XS_STRIDE * 2) + seg * 16,
                          g_W2t + (size_t)n * K2PAD + 32 + seg * 8);
            }
        }
        cpasync_commit();               // group 1
        cpasync_wait1();                // W2(0) ready
        __syncthreads();                // also covers Hs writes
    }
    // ---------------- layer-2 mainloop (A from Hs) ----------------
    for (int c = 0; c < L2C; ++c) {
        uint32_t wsb = ws_base[c % 3];
        if (c + 2 < L2C) {
            int s2 = (c + 2) % 3;
            int c2 = (c + 2) * 32;
            #pragma unroll
            for (int u = 0; u < 4; ++u) {
                int e = tid + u * 256;
                if (e < HID * 4) {
                    int n = e >> 2, seg = e & 3;
                    cpasync16(ws_base[s2] + n * (XS_STRIDE * 2) + seg * 16,
                              g_W2t + (size_t)n * K2PAD + c2 + seg * 8);
                }
            }
        }
        cpasync_commit();
        int c0 = c * 32;
        #pragma unroll
        for (int ks = 0; ks < 2; ++ks) {
            int kb = ks * 16;
            uint32_t a[2][4];
            #pragma unroll
            for (int mt = 0; mt < 2; ++mt)
                ldsm_x4(a[mt], hs_base + ((rowA + mt * 16) * HS_STRIDE + c0 + kb + colhA) * 2);
            #pragma unroll
            for (int t = 0; t < 7; ++t) {
                int nt_g = wn + 4 * t;
                if (nt_g < NTILES) {
                    uint32_t bb[2];
                    ldsm_x2(bb, wsb + ((nt_g * 8 + rowB) * XS_STRIDE + kb + colhB) * 2);
                    #pragma unroll
                    for (int mt = 0; mt < 2; ++mt)
                        mma16816(acc[mt][t], a[mt], bb);
                }
            }
        }
        if (c + 1 < L2C) cpasync_wait1();
        __syncthreads();
    }

    // ---------------- scoring epilogue ----------------
    #pragma unroll
    for (int mt = 0; mt < 2; ++mt) {
        #pragma unroll
        for (int half = 0; half < 2; ++half) {
            float sp = 0.f;
            #pragma unroll
            for (int t = 0; t < 7; ++t) {
                int nt_g = wn + 4 * t;
                if (nt_g < NTILES) {
                    int col = nt_g * 8 + 2 * l4;
                    float h0 = fmaxf(acc[mt][t][half * 2 + 0] + b2s[col], 0.f);
                    float h1 = fmaxf(acc[mt][t][half * 2 + 1] + b2s[col + 1], 0.f);
                    sp = fmaf(h0, W3s[col], sp);
                    sp = fmaf(h1, W3s[col + 1], sp);
                }
            }
            sp += __shfl_xor_sync(0xFFFFFFFFu, sp, 1);
            sp += __shfl_xor_sync(0xFFFFFFFFu, sp, 2);
            if (l4 == 0) {
                int r = wm * 32 + mt * 16 + q + 8 * half;
                sred[r][wn] = sp;
            }
        }
    }
    __syncthreads();
    if (tid < MTILE) {
        float s = sred[tid][0] + sred[tid][1] + sred[tid][2] + sred[tid][3] + b3[0];
        int i = bi * 8 + (tid >> 3), j = bj * 8 + (tid & 7);
        if (i > j)
            g_S[((size_t)b * NSEL + i) * NSEL + j] = s;
    }
}

// ---------------- row softmax + fill ----------------
__global__ void k_soft(float* __restrict__ out) {
    int bn = blockIdx.x;
    int i = bn % NSEL;
    const float* Srow = g_S + (size_t)bn * NSEL;
    float* orow = out + (size_t)bn * NSEL;
    __shared__ float red[256];
    int tid = threadIdx.x;

    float mx = -1e30f;
    for (int j = tid; j <= i; j += 256) {
        float l = (j == i) ? 0.f : Srow[j];
        mx = fmaxf(mx, l);
    }
    red[tid] = mx; __syncthreads();
    for (int s = 128; s > 0; s >>= 1) {
        if (tid < s) red[tid] = fmaxf(red[tid], red[tid + s]);
        __syncthreads();
    }
    mx = red[0]; __syncthreads();

    float sum = 0.f;
    for (int j = tid; j <= i; j += 256) {
        float l = (j == i) ? 0.f : Srow[j];
        sum += __expf(l - mx);
    }
    red[tid] = sum; __syncthreads();
    for (int s = 128; s > 0; s >>= 1) {
        if (tid < s) red[tid] += red[tid + s];
        __syncthreads();
    }
    sum = red[0];
    float inv = 1.0f / sum;

    for (int j = tid; j < NSEL; j += 256) {
        if (j <= i) {
            float l = (j == i) ? 0.f : Srow[j];
            orow[j] = __expf(l - mx) * inv;
        } else {
            orow[j] = -1000.0f;
        }
    }
}

// ---------------- launch ----------------
extern "C" void kernel_launch(void* const* d_in, const int* in_sizes, int n_in,
                              void* d_out, int out_size) {
    const float* emb = (const float*)d_in[0];
    const int*   idx = (const int*)  d_in[1];
    const float* W1  = (const float*)d_in[2];
    const float* b1  = (const float*)d_in[3];
    const float* W2  = (const float*)d_in[4];
    const float* b2  = (const float*)d_in[5];
    const float* W3  = (const float*)d_in[6];
    const float* b3  = (const float*)d_in[7];
    float* out = (float*)d_out;

    static int configured = 0;
    if (!configured) {
        cudaFuncSetAttribute(k_fused, cudaFuncAttributeMaxDynamicSharedMemorySize,
                             DYN_BYTES);
        configured = 1;
    }

    k_prep<<<PREP_BLKS, 256>>>(emb, idx, W1, W2);
    k_ab<<<dim3(16, 7), 256>>>(W1);
    k_fused<<<dim3(NBLK, BATCH), 256, DYN_BYTES>>>(b1, b2, W3, b3);
    k_soft<<<BATCH * NSEL, 256>>>(out);
}

// round 12
// speedup vs baseline: 1.1591x; 1.1591x over previous
#include <cuda_runtime.h>
#include <cuda_bf16.h>
#include <cuda_fp8.h>
#include <math.h>
#include <stdint.h>

#define BATCH 4
#define TLEN  4096
#define DIM   768
#define NSEL  256
#define HID   200
#define MTILE 64             // pairs per CTA (8x8 token block)
#define NB8   32
#define NBLK  528            // NB8*(NB8+1)/2
#define K2PAD 256            // padded K for layer 2 (4 chunks of 64)
#define L1C   (DIM / 64)     // 12 chunks of 64 fp8
#define L2C   (K2PAD / 64)   // 4
#define NTILES 25            // 200/8 n-tiles
#define XS_STRIDE 80         // BYTES per 64-fp8 row (16B pad, conflict-free)
#define HS_STRIDE 240        // BYTES per Hs row (224 fp8 + pad)

// dynamic smem layout (bytes)
#define XS0_OFF 0                      // 64*80 = 5120
#define XS1_OFF 5120
#define WS0_OFF 10240                  // 200*80 = 16000
#define WS1_OFF 26240
#define ES0_OFF 42240                  // 16 rows * 64 fp32 = 4096
#define ES1_OFF 46336
#define AB_OFF  50432                  // 16*200 fp32 = 12800
#define HS_OFF  63232                  // 64*240 = 15360
#define DYN_BYTES 78592

#define W_SCALE   32.0f
#define H_SCALE   8.0f
#define INV_W     (1.0f / 32.0f)
#define INV_HW    (1.0f / 256.0f)

// ---------------- device scratch ----------------
__device__ float    g_E  [BATCH * NSEL * DIM];
__device__ float    g_AB [BATCH * NSEL * 2 * HID];
__device__ uint8_t  g_W1q[HID * DIM];               // e4m3 of 32*W1c^T [h][d]
__device__ uint8_t  g_W2q[HID * K2PAD];             // e4m3 of 32*W2^T  [h][k]
__device__ float    g_S  [BATCH * NSEL * NSEL];

// ---------------- helpers ----------------
__device__ __forceinline__ void mma_fp8(float* c, const uint32_t* a, const uint32_t* b) {
    asm volatile(
        "mma.sync.aligned.m16n8k32.row.col.f32.e4m3.e4m3.f32 "
        "{%0,%1,%2,%3}, {%4,%5,%6,%7}, {%8,%9}, {%0,%1,%2,%3};"
        : "+f"(c[0]), "+f"(c[1]), "+f"(c[2]), "+f"(c[3])
        : "r"(a[0]), "r"(a[1]), "r"(a[2]), "r"(a[3]), "r"(b[0]), "r"(b[1]));
}
__device__ __forceinline__ void ldsm_x4(uint32_t* r, uint32_t addr) {
    asm volatile("ldmatrix.sync.aligned.m8n8.x4.shared.b16 {%0,%1,%2,%3}, [%4];"
                 : "=r"(r[0]), "=r"(r[1]), "=r"(r[2]), "=r"(r[3]) : "r"(addr));
}
__device__ __forceinline__ void ldsm_x2(uint32_t* r, uint32_t addr) {
    asm volatile("ldmatrix.sync.aligned.m8n8.x2.shared.b16 {%0,%1}, [%2];"
                 : "=r"(r[0]), "=r"(r[1]) : "r"(addr));
}
__device__ __forceinline__ void cpasync16(uint32_t smem_addr, const void* gsrc) {
    asm volatile("cp.async.cg.shared.global [%0], [%1], 16;"
                 :: "r"(smem_addr), "l"(gsrc) : "memory");
}
__device__ __forceinline__ void cpasync_commit() {
    asm volatile("cp.async.commit_group;" ::: "memory");
}
__device__ __forceinline__ void cpasync_wait0() {
    asm volatile("cp.async.wait_group 0;" ::: "memory");
}
// pack 4 floats -> 4 e4m3 bytes (k-ascending)
__device__ __forceinline__ uint32_t pack_e4m3_4(float a0, float a1, float a2, float a3) {
    uint16_t lo, hi;
    asm("cvt.rn.satfinite.e4m3x2.f32 %0, %1, %2;" : "=h"(lo) : "f"(a1), "f"(a0));
    asm("cvt.rn.satfinite.e4m3x2.f32 %0, %1, %2;" : "=h"(hi) : "f"(a3), "f"(a2));
    return (uint32_t)lo | ((uint32_t)hi << 16);
}
__device__ __forceinline__ uint16_t pack_e4m3_2(float a0, float a1) {
    uint16_t v;
    asm("cvt.rn.satfinite.e4m3x2.f32 %0, %1, %2;" : "=h"(v) : "f"(a1), "f"(a0));
    return v;
}

// ---------------- fused prep: gather + W1q + W2q ----------------
#define PREP_GATH  (BATCH * NSEL)                       // 1024
#define PREP_W1    ((HID * DIM + 255) / 256)            // 600
#define PREP_W2    ((HID * K2PAD + 255) / 256)          // 200
#define PREP_BLKS  (PREP_GATH + PREP_W1 + PREP_W2)

__global__ void k_prep(const float* __restrict__ emb, const int* __restrict__ idx,
                       const float* __restrict__ W1, const float* __restrict__ W2) {
    int blk = blockIdx.x;
    int tid = threadIdx.x;
    if (blk < PREP_GATH) {
        int b = blk / NSEL, n = blk % NSEL;
        int t = idx[b * NSEL + n];
        const float4* src = (const float4*)(emb + ((size_t)b * TLEN + t) * DIM);
        float4* dst = (float4*)(g_E + (size_t)blk * DIM);
        if (tid < DIM / 4) dst[tid] = src[tid];
        return;
    }
    blk -= PREP_GATH;
    if (blk < PREP_W1) {
        int e = blk * 256 + tid;
        if (e < HID * DIM) {
            int h = e / DIM, d = e % DIM;
            float v = W_SCALE * W1[(size_t)(2 * DIM + d) * HID + h];
            g_W1q[e] = (uint8_t)__nv_cvt_float_to_fp8(v, __NV_SATFINITE, __NV_E4M3);
        }
        return;
    }
    blk -= PREP_W1;
    {
        int e = blk * 256 + tid;
        if (e < HID * K2PAD) {
            int h = e / K2PAD, k = e % K2PAD;
            float v = (k < HID) ? W_SCALE * W2[(size_t)k * HID + h] : 0.f;
            g_W2q[e] = (uint8_t)__nv_cvt_float_to_fp8(v, __NV_SATFINITE, __NV_E4M3);
        }
    }
}

// ---------------- exact A/B partials (fp32 SIMT, small) ----------------
__global__ void k_ab(const float* __restrict__ W1) {
    __shared__ __align__(16) float As[16][64 + 4];
    __shared__ __align__(16) float Bs[16][64 + 4];
    int bm = blockIdx.x * 64, bn = blockIdx.y * 64;
    int tx = threadIdx.x % 16, ty = threadIdx.x / 16;
    float acc[4][4] = {};
    for (int k0 = 0; k0 < DIM; k0 += 16) {
        for (int t = threadIdx.x; t < 1024; t += 256) {
            int k = t % 16, m = t / 16;
            As[k][m] = g_E[(size_t)(bm + m) * DIM + k0 + k];
        }
        for (int t = threadIdx.x; t < 1024; t += 256) {
            int n = t % 64, k = t / 64;
            int c = bn + n;
            float v = 0.f;
            if (c < 2 * HID) {
                int half = c / HID, h = c - half * HID;
                v = W1[(size_t)(half * DIM + k0 + k) * HID + h];
            }
            Bs[k][n] = v;
        }
        __syncthreads();
        #pragma unroll
        for (int k = 0; k < 16; ++k) {
            float a[4], bb[4];
            #pragma unroll
            for (int u = 0; u < 4; ++u) a[u] = As[k][ty * 4 + u];
            #pragma unroll
            for (int v = 0; v < 4; ++v) bb[v] = Bs[k][tx * 4 + v];
            #pragma unroll
            for (int u = 0; u < 4; ++u)
                #pragma unroll
                for (int v = 0; v < 4; ++v)
                    acc[u][v] = fmaf(a[u], bb[v], acc[u][v]);
        }
        __syncthreads();
    }
    #pragma unroll
    for (int u = 0; u < 4; ++u)
        #pragma unroll
        for (int v = 0; v < 4; ++v) {
            int c = bn + tx * 4 + v;
            if (c < 2 * HID)
                g_AB[(size_t)(bm + ty * 4 + u) * (2 * HID) + c] = acc[u][v];
        }
}

// ================= fused MLP (pair-blocked, FP8 e4m3 MMA) =================
__global__ __launch_bounds__(256, 2)
void k_fused(const float* __restrict__ b1, const float* __restrict__ b2,
             const float* __restrict__ W3, const float* __restrict__ b3) {
    extern __shared__ __align__(16) char dynsm[];
    uint32_t dynbase = (uint32_t)__cvta_generic_to_shared(dynsm);
    uint32_t xs_base[2] = { dynbase + XS0_OFF, dynbase + XS1_OFF };
    uint32_t ws_base[2] = { dynbase + WS0_OFF, dynbase + WS1_OFF };
    uint32_t es_base[2] = { dynbase + ES0_OFF, dynbase + ES1_OFF };
    uint32_t ab_base = dynbase + AB_OFF;
    uint32_t hs_base = dynbase + HS_OFF;
    uint8_t* XsBuf[2] = { (uint8_t*)(dynsm + XS0_OFF), (uint8_t*)(dynsm + XS1_OFF) };
    float*   EsBuf[2] = { (float*)(dynsm + ES0_OFF), (float*)(dynsm + ES1_OFF) };
    float*   sAB = (float*)(dynsm + AB_OFF);            // [16][200]
    uint8_t* Hs  = (uint8_t*)(dynsm + HS_OFF);

    __shared__ float b1s[HID], b2s[HID], W3s[HID];
    __shared__ float sred[MTILE][4];

    int tid = threadIdx.x;
    int b = blockIdx.y;

    // decode token block (bi, bj), bi >= bj
    int tb = blockIdx.x;
    int bi = (int)((sqrtf(8.0f * (float)tb + 1.0f) - 1.0f) * 0.5f);
    while (bi * (bi + 1) / 2 > tb) --bi;
    while ((bi + 1) * (bi + 2) / 2 <= tb) ++bi;
    int bj = tb - bi * (bi + 1) / 2;

    if (tid < HID) { b1s[tid] = b1[tid]; b2s[tid] = b2[tid]; W3s[tid] = W3[tid]; }

    const float* Eb = g_E + (size_t)b * NSEL * DIM;
    int wid = tid / 32, lane = tid % 32;
    int wm = wid & 1, wn = wid >> 1;
    int q = lane >> 2, l4 = lane & 3;

    // ldmatrix per-thread address components (BYTES)
    int rowA = wm * 32 + (lane & 15);          // + mt*16
    int colA = (lane >> 4) * 16;               // byte col-tile
    int rowB = lane & 7;                       // + nt_g*8
    int colB = ((lane >> 3) & 1) * 16;

    // E fill coords: 16 rows x 16 segs of 16B
    int er = tid >> 4, eseg = tid & 15;
    int etok = (er < 8) ? (bi * 8 + er) : (bj * 8 + er - 8);
    const float* esrc_row = Eb + (size_t)etok * DIM + eseg * 4;
    uint32_t edst = (uint32_t)(er * 256 + eseg * 16);

    // X build coords: 64 rows x 16 u32 (4 fp8 each); 4 slots/thread
    int xr[4], xc[4];
    #pragma unroll
    for (int u = 0; u < 4; ++u) {
        int e = tid + u * 256;
        xr[u] = e >> 4;
        xc[u] = (e & 15) * 4;                  // float index within 64-chunk / byte offset
    }

    float acc[2][7][4];
    #pragma unroll
    for (int mt = 0; mt < 2; ++mt)
        #pragma unroll
        for (int t = 0; t < 7; ++t)
            #pragma unroll
            for (int v = 0; v < 4; ++v) acc[mt][t][v] = 0.f;

    // ---------------- prologue: AB + E(0) + W1(0) ----------------
    {
        #pragma unroll
        for (int u = 0; u < 4; ++u) {
            int e = tid + u * 256;
            if (e < 800) {
                int row = e / 50, seg = e % 50;
                int tok = (row < 8) ? (bi * 8 + row) : (bj * 8 + row - 8);
                int foff = (row < 8) ? 0 : HID;
                cpasync16(ab_base + (row * HID + seg * 4) * 4,
                          g_AB + ((size_t)(b * NSEL + tok)) * (2 * HID) + foff + seg * 4);
            }
        }
        cpasync16(es_base[0] + edst, esrc_row);
        #pragma unroll
        for (int u = 0; u < 4; ++u) {
            int e = tid + u * 256;
            if (e < HID * 4) {
                int n = e >> 2, seg = e & 3;
                cpasync16(ws_base[0] + n * XS_STRIDE + seg * 16,
                          g_W1q + (size_t)n * DIM + seg * 16);
            }
        }
        cpasync_commit();
        cpasync_wait0();
        __syncthreads();
        #pragma unroll
        for (int u = 0; u < 4; ++u) {
            int ri = xr[u] >> 3, rj = xr[u] & 7;
            const float4 xi = *(const float4*)&EsBuf[0][ri * 64 + xc[u]];
            const float4 xj = *(const float4*)&EsBuf[0][(8 + rj) * 64 + xc[u]];
            *(uint32_t*)&XsBuf[0][xr[u] * XS_STRIDE + xc[u]] =
                pack_e4m3_4(xi.x * xj.x, xi.y * xj.y, xi.z * xj.z, xi.w * xj.w);
        }
        __syncthreads();
    }

    // ---------------- layer-1 mainloop (chunks of 64 K) ----------------
    for (int c = 0; c < L1C; ++c) {
        uint32_t xsb = xs_base[c & 1];
        uint32_t wsb = ws_base[c & 1];
        int nb = (c + 1) & 1;
        bool more = (c + 1 < L1C);
        int c1 = (c + 1) * 64;

        if (more) {
            cpasync16(es_base[nb] + edst, esrc_row + c1);
            #pragma unroll
            for (int u = 0; u < 4; ++u) {
                int e = tid + u * 256;
                if (e < HID * 4) {
                    int n = e >> 2, seg = e & 3;
                    cpasync16(ws_base[nb] + n * XS_STRIDE + seg * 16,
                              g_W1q + (size_t)n * DIM + c1 + seg * 16);
                }
            }
            cpasync_commit();
        }
        // MMA(c): 2 k32 steps
        #pragma unroll
        for (int ks = 0; ks < 2; ++ks) {
            int kb = ks * 32;
            uint32_t a[2][4];
            #pragma unroll
            for (int mt = 0; mt < 2; ++mt)
                ldsm_x4(a[mt], xsb + (rowA + mt * 16) * XS_STRIDE + kb + colA);
            #pragma unroll
            for (int t = 0; t < 7; ++t) {
                int nt_g = wn + 4 * t;
                if (nt_g < NTILES) {
                    uint32_t bb[2];
                    ldsm_x2(bb, wsb + (nt_g * 8 + rowB) * XS_STRIDE + kb + colB);
                    #pragma unroll
                    for (int mt = 0; mt < 2; ++mt)
                        mma_fp8(acc[mt][t], a[mt], bb);
                }
            }
        }
        if (more) {
            cpasync_wait0();
            #pragma unroll
            for (int u = 0; u < 4; ++u) {
                int ri = xr[u] >> 3, rj = xr[u] & 7;
                const float4 xi = *(const float4*)&EsBuf[nb][ri * 64 + xc[u]];
                const float4 xj = *(const float4*)&EsBuf[nb][(8 + rj) * 64 + xc[u]];
                *(uint32_t*)&XsBuf[nb][xr[u] * XS_STRIDE + xc[u]] =
                    pack_e4m3_4(xi.x * xj.x, xi.y * xj.y, xi.z * xj.z, xi.w * xj.w);
            }
        }
        __syncthreads();
    }

    // ---------------- layer-1 epilogue -> Hs (e4m3, x8 scale) ----------------
    #pragma unroll
    for (int mt = 0; mt < 2; ++mt) {
        #pragma unroll
        for (int half = 0; half < 2; ++half) {
            int r = wm * 32 + mt * 16 + q + 8 * half;
            int ri = r >> 3, rj = r & 7;
            #pragma unroll
            for (int t = 0; t < 7; ++t) {
                int nt_g = wn + 4 * t;
                if (nt_g < NTILES) {
                    int col = nt_g * 8 + 2 * l4;
                    float2 ai = *(const float2*)&sAB[ri * HID + col];
                    float2 bj = *(const float2*)&sAB[(8 + rj) * HID + col];
                    float v0 = acc[mt][t][half * 2 + 0] * INV_W + ai.x + bj.x + b1s[col];
                    float v1 = acc[mt][t][half * 2 + 1] * INV_W + ai.y + bj.y + b1s[col + 1];
                    uint16_t p = pack_e4m3_2(H_SCALE * fmaxf(v0, 0.f),
                                             H_SCALE * fmaxf(v1, 0.f));
                    *(uint16_t*)(Hs + r * HS_STRIDE + col) = p;
                }
            }
        }
    }
    // zero pad cols [200,256)
    for (int e = tid; e < MTILE * 14; e += 256) {
        int r = e / 14, cc = HID + (e % 14) * 4;
        *(uint32_t*)(Hs + r * HS_STRIDE + cc) = 0u;
    }

    #pragma unroll
    for (int mt = 0; mt < 2; ++mt)
        #pragma unroll
        for (int t = 0; t < 7; ++t)
            #pragma unroll
            for (int v = 0; v < 4; ++v) acc[mt][t][v] = 0.f;

    // ---------------- layer-2 prologue ----------------
    {
        #pragma unroll
        for (int u = 0; u < 4; ++u) {
            int e = tid + u * 256;
            if (e < HID * 4) {
                int n = e >> 2, seg = e & 3;
                cpasync16(ws_base[0] + n * XS_STRIDE + seg * 16,
                          g_W2q + (size_t)n * K2PAD + seg * 16);
            }
        }
        cpasync_commit();
        cpasync_wait0();
        __syncthreads();            // covers Hs writes + W2(0)
    }
    // ---------------- layer-2 mainloop (A from Hs fp8) ----------------
    for (int c = 0; c < L2C; ++c) {
        uint32_t wsb = ws_base[c & 1];
        int nb = (c + 1) & 1;
        bool more = (c + 1 < L2C);
        if (more) {
            int c1 = (c + 1) * 64;
            #pragma unroll
            for (int u = 0; u < 4; ++u) {
                int e = tid + u * 256;
                if (e < HID * 4) {
                    int n = e >> 2, seg = e & 3;
                    cpasync16(ws_base[nb] + n * XS_STRIDE + seg * 16,
                              g_W2q + (size_t)n * K2PAD + c1 + seg * 16);
                }
            }
            cpasync_commit();
        }
        int c0 = c * 64;
        #pragma unroll
        for (int ks = 0; ks < 2; ++ks) {
            int kb = ks * 32;
            uint32_t a[2][4];
            #pragma unroll
            for (int mt = 0; mt < 2; ++mt)
                ldsm_x4(a[mt], hs_base + (rowA + mt * 16) * HS_STRIDE + c0 + kb + colA);
            #pragma unroll
            for (int t = 0; t < 7; ++t) {
                int nt_g = wn + 4 * t;
                if (nt_g < NTILES) {
                    uint32_t bb[2];
                    ldsm_x2(bb, wsb + (nt_g * 8 + rowB) * XS_STRIDE + kb + colB);
                    #pragma unroll
                    for (int mt = 0; mt < 2; ++mt)
                        mma_fp8(acc[mt][t], a[mt], bb);
                }
            }
        }
        if (more) cpasync_wait0();
        __syncthreads();
    }

    // ---------------- scoring epilogue ----------------
    #pragma unroll
    for (int mt = 0; mt < 2; ++mt) {
        #pragma unroll
        for (int half = 0; half < 2; ++half) {
            float sp = 0.f;
            #pragma unroll
            for (int t = 0; t < 7; ++t) {
                int nt_g = wn + 4 * t;
                if (nt_g < NTILES) {
                    int col = nt_g * 8 + 2 * l4;
                    float h0 = fmaxf(acc[mt][t][half * 2 + 0] * INV_HW + b2s[col], 0.f);
                    float h1 = fmaxf(acc[mt][t][half * 2 + 1] * INV_HW + b2s[col + 1], 0.f);
                    sp = fmaf(h0, W3s[col], sp);
                    sp = fmaf(h1, W3s[col + 1], sp);
                }
            }
            sp += __shfl_xor_sync(0xFFFFFFFFu, sp, 1);
            sp += __shfl_xor_sync(0xFFFFFFFFu, sp, 2);
            if (l4 == 0) {
                int r = wm * 32 + mt * 16 + q + 8 * half;
                sred[r][wn] = sp;
            }
        }
    }
    __syncthreads();
    if (tid < MTILE) {
        float s = sred[tid][0] + sred[tid][1] + sred[tid][2] + sred[tid][3] + b3[0];
        int i = bi * 8 + (tid >> 3), j = bj * 8 + (tid & 7);
        if (i > j)
            g_S[((size_t)b * NSEL + i) * NSEL + j] = s;
    }
}

// ---------------- row softmax + fill ----------------
__global__ void k_soft(float* __restrict__ out) {
    int bn = blockIdx.x;
    int i = bn % NSEL;
    const float* Srow = g_S + (size_t)bn * NSEL;
    float* orow = out + (size_t)bn * NSEL;
    __shared__ float red[256];
    int tid = threadIdx.x;

    float mx = -1e30f;
    for (int j = tid; j <= i; j += 256) {
        float l = (j == i) ? 0.f : Srow[j];
        mx = fmaxf(mx, l);
    }
    red[tid] = mx; __syncthreads();
    for (int s = 128; s > 0; s >>= 1) {
        if (tid < s) red[tid] = fmaxf(red[tid], red[tid + s]);
        __syncthreads();
    }
    mx = red[0]; __syncthreads();

    float sum = 0.f;
    for (int j = tid; j <= i; j += 256) {
        float l = (j == i) ? 0.f : Srow[j];
        sum += __expf(l - mx);
    }
    red[tid] = sum; __syncthreads();
    for (int s = 128; s > 0; s >>= 1) {
        if (tid < s) red[tid] += red[tid + s];
        __syncthreads();
    }
    sum = red[0];
    float inv = 1.0f / sum;

    for (int j = tid; j < NSEL; j += 256) {
        if (j <= i) {
            float l = (j == i) ? 0.f : Srow[j];
            orow[j] = __expf(l - mx) * inv;
        } else {
            orow[j] = -1000.0f;
        }
    }
}

// ---------------- launch ----------------
extern "C" void kernel_launch(void* const* d_in, const int* in_sizes, int n_in,
                              void* d_out, int out_size) {
    const float* emb = (const float*)d_in[0];
    const int*   idx = (const int*)  d_in[1];
    const float* W1  = (const float*)d_in[2];
    const float* b1  = (const float*)d_in[3];
    const float* W2  = (const float*)d_in[4];
    const float* b2  = (const float*)d_in[5];
    const float* W3  = (const float*)d_in[6];
    const float* b3  = (const float*)d_in[7];
    float* out = (float*)d_out;

    static int configured = 0;
    if (!configured) {
        cudaFuncSetAttribute(k_fused, cudaFuncAttributeMaxDynamicSharedMemorySize,
                             DYN_BYTES);
        configured = 1;
    }

    k_prep<<<PREP_BLKS, 256>>>(emb, idx, W1, W2);
    k_ab<<<dim3(16, 7), 256>>>(W1);
    k_fused<<<dim3(NBLK, BATCH), 256, DYN_BYTES>>>(b1, b2, W3, b3);
    k_soft<<<BATCH * NSEL, 256>>>(out);
}

// round 13
// speedup vs baseline: 1.1862x; 1.0233x over previous
#include <cuda_runtime.h>
#include <cuda_bf16.h>
#include <cuda_fp8.h>
#include <math.h>
#include <stdint.h>

#define BATCH 4
#define TLEN  4096
#define DIM   768
#define NSEL  256
#define HID   200
#define MTILE 64             // pairs per CTA (8x8 token block)
#define NB8   32
#define NBLK  528            // NB8*(NB8+1)/2
#define K2PAD 256
#define L1C   (DIM / 64)     // 12 chunks of 64 fp8
#define L2C   4              // 256/64
#define NTILES 25
#define XR    784            // X row stride bytes (768 + 16 pad), conflict-free
#define WS_STRIDE 80         // W chunk row stride bytes
#define HS_STRIDE 240        // Hs row stride bytes

// dynamic smem layout (bytes)
#define X_OFF   0                      // 64*784 = 50176
#define WS0_OFF 50176                  // 200*80 = 16000
#define WS1_OFF 66176                  // 16000
#define HS_OFF  82176                  // 64*240 = 15360
#define DYN_BYTES 97536
#define ES_OFF  WS0_OFF                // E fp32 half staging overlays W ring (24576 <= 32000)

#define W_SCALE   32.0f
#define H_SCALE   8.0f
#define INV_W     (1.0f / 32.0f)
#define INV_HW    (1.0f / 256.0f)

// ---------------- device scratch ----------------
__device__ float    g_E  [BATCH * NSEL * DIM];
__device__ float    g_AB [BATCH * NSEL * 2 * HID];
__device__ uint8_t  g_W1q[HID * DIM];               // e4m3 of 32*W1c^T [h][d]
__device__ uint8_t  g_W2q[HID * K2PAD];             // e4m3 of 32*W2^T  [h][k]
__device__ float    g_S  [BATCH * NSEL * NSEL];

// ---------------- helpers ----------------
__device__ __forceinline__ void mma_fp8(float* c, const uint32_t* a, const uint32_t* b) {
    asm volatile(
        "mma.sync.aligned.m16n8k32.row.col.f32.e4m3.e4m3.f32 "
        "{%0,%1,%2,%3}, {%4,%5,%6,%7}, {%8,%9}, {%0,%1,%2,%3};"
        : "+f"(c[0]), "+f"(c[1]), "+f"(c[2]), "+f"(c[3])
        : "r"(a[0]), "r"(a[1]), "r"(a[2]), "r"(a[3]), "r"(b[0]), "r"(b[1]));
}
__device__ __forceinline__ void ldsm_x4(uint32_t* r, uint32_t addr) {
    asm volatile("ldmatrix.sync.aligned.m8n8.x4.shared.b16 {%0,%1,%2,%3}, [%4];"
                 : "=r"(r[0]), "=r"(r[1]), "=r"(r[2]), "=r"(r[3]) : "r"(addr));
}
__device__ __forceinline__ void cpasync16(uint32_t smem_addr, const void* gsrc) {
    asm volatile("cp.async.cg.shared.global [%0], [%1], 16;"
                 :: "r"(smem_addr), "l"(gsrc) : "memory");
}
__device__ __forceinline__ void cpasync_commit() {
    asm volatile("cp.async.commit_group;" ::: "memory");
}
__device__ __forceinline__ void cpasync_wait0() {
    asm volatile("cp.async.wait_group 0;" ::: "memory");
}
__device__ __forceinline__ uint32_t pack_e4m3_4(float a0, float a1, float a2, float a3) {
    uint16_t lo, hi;
    asm("cvt.rn.satfinite.e4m3x2.f32 %0, %1, %2;" : "=h"(lo) : "f"(a1), "f"(a0));
    asm("cvt.rn.satfinite.e4m3x2.f32 %0, %1, %2;" : "=h"(hi) : "f"(a3), "f"(a2));
    return (uint32_t)lo | ((uint32_t)hi << 16);
}
__device__ __forceinline__ uint16_t pack_e4m3_2(float a0, float a1) {
    uint16_t v;
    asm("cvt.rn.satfinite.e4m3x2.f32 %0, %1, %2;" : "=h"(v) : "f"(a1), "f"(a0));
    return v;
}

// ---------------- no-op (ncu launch-index alignment: k_fused = launch #5) ----------------
__global__ void k_nop() {}

// ---------------- fused prep: gather + W1q + W2q ----------------
#define PREP_GATH  (BATCH * NSEL)                       // 1024
#define PREP_W1    ((HID * DIM + 255) / 256)            // 600
#define PREP_W2    ((HID * K2PAD + 255) / 256)          // 200
#define PREP_BLKS  (PREP_GATH + PREP_W1 + PREP_W2)

__global__ void k_prep(const float* __restrict__ emb, const int* __restrict__ idx,
                       const float* __restrict__ W1, const float* __restrict__ W2) {
    int blk = blockIdx.x;
    int tid = threadIdx.x;
    if (blk < PREP_GATH) {
        int b = blk / NSEL, n = blk % NSEL;
        int t = idx[b * NSEL + n];
        const float4* src = (const float4*)(emb + ((size_t)b * TLEN + t) * DIM);
        float4* dst = (float4*)(g_E + (size_t)blk * DIM);
        if (tid < DIM / 4) dst[tid] = src[tid];
        return;
    }
    blk -= PREP_GATH;
    if (blk < PREP_W1) {
        int e = blk * 256 + tid;
        if (e < HID * DIM) {
            int h = e / DIM, d = e % DIM;
            float v = W_SCALE * W1[(size_t)(2 * DIM + d) * HID + h];
            g_W1q[e] = (uint8_t)__nv_cvt_float_to_fp8(v, __NV_SATFINITE, __NV_E4M3);
        }
        return;
    }
    blk -= PREP_W1;
    {
        int e = blk * 256 + tid;
        if (e < HID * K2PAD) {
            int h = e / K2PAD, k = e % K2PAD;
            float v = (k < HID) ? W_SCALE * W2[(size_t)k * HID + h] : 0.f;
            g_W2q[e] = (uint8_t)__nv_cvt_float_to_fp8(v, __NV_SATFINITE, __NV_E4M3);
        }
    }
}

// ---------------- exact A/B partials (fp32 SIMT, small) ----------------
__global__ void k_ab(const float* __restrict__ W1) {
    __shared__ __align__(16) float As[16][64 + 4];
    __shared__ __align__(16) float Bs[16][64 + 4];
    int bm = blockIdx.x * 64, bn = blockIdx.y * 64;
    int tx = threadIdx.x % 16, ty = threadIdx.x / 16;
    float acc[4][4] = {};
    for (int k0 = 0; k0 < DIM; k0 += 16) {
        for (int t = threadIdx.x; t < 1024; t += 256) {
            int k = t % 16, m = t / 16;
            As[k][m] = g_E[(size_t)(bm + m) * DIM + k0 + k];
        }
        for (int t = threadIdx.x; t < 1024; t += 256) {
            int n = t % 64, k = t / 64;
            int c = bn + n;
            float v = 0.f;
            if (c < 2 * HID) {
                int half = c / HID, h = c - half * HID;
                v = W1[(size_t)(half * DIM + k0 + k) * HID + h];
            }
            Bs[k][n] = v;
        }
        __syncthreads();
        #pragma unroll
        for (int k = 0; k < 16; ++k) {
            float a[4], bb[4];
            #pragma unroll
            for (int u = 0; u < 4; ++u) a[u] = As[k][ty * 4 + u];
            #pragma unroll
            for (int v = 0; v < 4; ++v) bb[v] = Bs[k][tx * 4 + v];
            #pragma unroll
            for (int u = 0; u < 4; ++u)
                #pragma unroll
                for (int v = 0; v < 4; ++v)
                    acc[u][v] = fmaf(a[u], bb[v], acc[u][v]);
        }
        __syncthreads();
    }
    #pragma unroll
    for (int u = 0; u < 4; ++u)
        #pragma unroll
        for (int v = 0; v < 4; ++v) {
            int c = bn + tx * 4 + v;
            if (c < 2 * HID)
                g_AB[(size_t)(bm + ty * 4 + u) * (2 * HID) + c] = acc[u][v];
        }
}

// ================= fused MLP (X fully smem-resident, FP8 MMA) =================
__global__ __launch_bounds__(256, 2)
void k_fused(const float* __restrict__ b1, const float* __restrict__ b2,
             const float* __restrict__ W3, const float* __restrict__ b3) {
    extern __shared__ __align__(16) char dynsm[];
    uint32_t dynbase = (uint32_t)__cvta_generic_to_shared(dynsm);
    uint32_t x_base = dynbase + X_OFF;
    uint32_t ws_base[2] = { dynbase + WS0_OFF, dynbase + WS1_OFF };
    uint32_t es_base = dynbase + ES_OFF;
    uint32_t hs_base = dynbase + HS_OFF;
    uint8_t* Xs = (uint8_t*)(dynsm + X_OFF);
    float*   Es = (float*)(dynsm + ES_OFF);              // [16][384] fp32 staging
    uint8_t* Hs = (uint8_t*)(dynsm + HS_OFF);

    __shared__ float b1s[HID], b2s[HID], W3s[HID];
    __shared__ float sred[MTILE][4];

    int tid = threadIdx.x;
    int b = blockIdx.y;

    // decode token block (bi, bj), bi >= bj
    int tb = blockIdx.x;
    int bi = (int)((sqrtf(8.0f * (float)tb + 1.0f) - 1.0f) * 0.5f);
    while (bi * (bi + 1) / 2 > tb) --bi;
    while ((bi + 1) * (bi + 2) / 2 <= tb) ++bi;
    int bj = tb - bi * (bi + 1) / 2;

    if (tid < HID) { b1s[tid] = b1[tid]; b2s[tid] = b2[tid]; W3s[tid] = W3[tid]; }

    const float* Eb = g_E + (size_t)b * NSEL * DIM;
    int wid = tid / 32, lane = tid % 32;
    int wm = wid & 1, wn = wid >> 1;
    int q = lane >> 2, l4 = lane & 3;

    // ldmatrix address components (bytes)
    int rowA  = wm * 32 + (lane & 15);         // + mt*16
    int colA  = (lane >> 4) * 16;
    int rowB8 = lane & 7;                      // + nt_g*8
    int colB4 = (lane >> 3) * 16;              // 0..48 (x4: both k32 halves)

    // ---------------- prologue A: build full X (two halves of 384 cols) ----------------
    #pragma unroll
    for (int h = 0; h < 2; ++h) {
        int hc = h * 384;
        // stage E fp32: 16 rows x 384 floats = 1536 segs of 16B
        #pragma unroll
        for (int u = 0; u < 6; ++u) {
            int seg = tid + u * 256;
            int row = seg / 96, sc = seg % 96;
            int tok = (row < 8) ? (bi * 8 + row) : (bj * 8 + row - 8);
            cpasync16(es_base + row * 1536 + sc * 16,
                      Eb + (size_t)tok * DIM + hc + sc * 4);
        }
        cpasync_commit();
        cpasync_wait0();
        __syncthreads();
        // build X cols [hc, hc+384): 6144 packs
        #pragma unroll
        for (int u = 0; u < 24; ++u) {
            int e = tid + u * 256;
            int row = e / 96, pc = e % 96;
            int ri = row >> 3, rj = row & 7;
            const float4 xi = *(const float4*)&Es[ri * 384 + pc * 4];
            const float4 xj = *(const float4*)&Es[(8 + rj) * 384 + pc * 4];
            *(uint32_t*)&Xs[row * XR + hc + pc * 4] =
                pack_e4m3_4(xi.x * xj.x, xi.y * xj.y, xi.z * xj.z, xi.w * xj.w);
        }
        __syncthreads();
    }

    float acc[2][7][4];
    #pragma unroll
    for (int mt = 0; mt < 2; ++mt)
        #pragma unroll
        for (int t = 0; t < 7; ++t)
            #pragma unroll
            for (int v = 0; v < 4; ++v) acc[mt][t][v] = 0.f;

    // ---------------- prologue B: W1 chunk 0 ----------------
    {
        #pragma unroll
        for (int u = 0; u < 4; ++u) {
            int e = tid + u * 256;
            if (e < HID * 4) {
                int n = e >> 2, seg = e & 3;
                cpasync16(ws_base[0] + n * WS_STRIDE + seg * 16,
                          g_W1q + (size_t)n * DIM + seg * 16);
            }
        }
        cpasync_commit();
        cpasync_wait0();
        __syncthreads();
    }

    // ---------------- layer-1 mainloop (12 chunks of 64 K; X resident) ----------------
    for (int c = 0; c < L1C; ++c) {
        uint32_t wsb = ws_base[c & 1];
        bool more = (c + 1 < L1C);
        if (more) {
            int c1 = (c + 1) * 64;
            #pragma unroll
            for (int u = 0; u < 4; ++u) {
                int e = tid + u * 256;
                if (e < HID * 4) {
                    int n = e >> 2, seg = e & 3;
                    cpasync16(ws_base[(c + 1) & 1] + n * WS_STRIDE + seg * 16,
                              g_W1q + (size_t)n * DIM + c1 + seg * 16);
                }
            }
            cpasync_commit();
        }
        // A fragments for both k32 steps
        uint32_t a[2][2][4];
        #pragma unroll
        for (int ks = 0; ks < 2; ++ks)
            #pragma unroll
            for (int mt = 0; mt < 2; ++mt)
                ldsm_x4(a[ks][mt],
                        x_base + (rowA + mt * 16) * XR + c * 64 + ks * 32 + colA);
        #pragma unroll
        for (int t = 0; t < 7; ++t) {
            int nt_g = wn + 4 * t;
            if (nt_g < NTILES) {
                uint32_t bb[4];
                ldsm_x4(bb, wsb + (nt_g * 8 + rowB8) * WS_STRIDE + colB4);
                #pragma unroll
                for (int ks = 0; ks < 2; ++ks)
                    #pragma unroll
                    for (int mt = 0; mt < 2; ++mt)
                        mma_fp8(acc[mt][t], a[ks][mt], bb + ks * 2);
            }
        }
        if (more) cpasync_wait0();
        __syncthreads();
    }

    // ---------------- layer-1 epilogue -> Hs (e4m3 x8); AB from global ----------------
    {
        const float* ABb = g_AB + (size_t)b * NSEL * (2 * HID);
        #pragma unroll
        for (int mt = 0; mt < 2; ++mt) {
            #pragma unroll
            for (int half = 0; half < 2; ++half) {
                int r = wm * 32 + mt * 16 + q + 8 * half;
                int ri = r >> 3, rj = r & 7;
                const float* Ai = ABb + (size_t)(bi * 8 + ri) * (2 * HID);
                const float* Bj = ABb + (size_t)(bj * 8 + rj) * (2 * HID) + HID;
                #pragma unroll
                for (int t = 0; t < 7; ++t) {
                    int nt_g = wn + 4 * t;
                    if (nt_g < NTILES) {
                        int col = nt_g * 8 + 2 * l4;
                        float2 ai = *(const float2*)(Ai + col);
                        float2 bj2 = *(const float2*)(Bj + col);
                        float v0 = acc[mt][t][half * 2 + 0] * INV_W + ai.x + bj2.x + b1s[col];
                        float v1 = acc[mt][t][half * 2 + 1] * INV_W + ai.y + bj2.y + b1s[col + 1];
                        uint16_t p = pack_e4m3_2(H_SCALE * fmaxf(v0, 0.f),
                                                 H_SCALE * fmaxf(v1, 0.f));
                        *(uint16_t*)(Hs + r * HS_STRIDE + col) = p;
                    }
                }
            }
        }
    }
    // zero pad cols [200,240)
    for (int e = tid; e < MTILE * 10; e += 256) {
        int r = e / 10, cc = HID + (e % 10) * 4;
        *(uint32_t*)(Hs + r * HS_STRIDE + cc) = 0u;
    }

    #pragma unroll
    for (int mt = 0; mt < 2; ++mt)
        #pragma unroll
        for (int t = 0; t < 7; ++t)
            #pragma unroll
            for (int v = 0; v < 4; ++v) acc[mt][t][v] = 0.f;

    // ---------------- layer-2 prologue ----------------
    {
        #pragma unroll
        for (int u = 0; u < 4; ++u) {
            int e = tid + u * 256;
            if (e < HID * 4) {
                int n = e >> 2, seg = e & 3;
                cpasync16(ws_base[0] + n * WS_STRIDE + seg * 16,
                          g_W2q + (size_t)n * K2PAD + seg * 16);
            }
        }
        cpasync_commit();
        cpasync_wait0();
        __syncthreads();            // covers Hs writes + W2(0)
    }
    // ---------------- layer-2 mainloop (A from Hs fp8; zero-weight tail guards) ----------------
    for (int c = 0; c < L2C; ++c) {
        uint32_t wsb = ws_base[c & 1];
        bool more = (c + 1 < L2C);
        if (more) {
            int c1 = (c + 1) * 64;
            #pragma unroll
            for (int u = 0; u < 4; ++u) {
                int e = tid + u * 256;
                if (e < HID * 4) {
                    int n = e >> 2, seg = e & 3;
                    cpasync16(ws_base[(c + 1) & 1] + n * WS_STRIDE + seg * 16,
                              g_W2q + (size_t)n * K2PAD + c1 + seg * 16);
                }
            }
            cpasync_commit();
        }
        uint32_t a[2][2][4];
        #pragma unroll
        for (int ks = 0; ks < 2; ++ks)
            #pragma unroll
            for (int mt = 0; mt < 2; ++mt)
                ldsm_x4(a[ks][mt],
                        hs_base + (rowA + mt * 16) * HS_STRIDE + c * 64 + ks * 32 + colA);
        #pragma unroll
        for (int t = 0; t < 7; ++t) {
            int nt_g = wn + 4 * t;
            if (nt_g < NTILES) {
                uint32_t bb[4];
                ldsm_x4(bb, wsb + (nt_g * 8 + rowB8) * WS_STRIDE + colB4);
                #pragma unroll
                for (int ks = 0; ks < 2; ++ks)
                    #pragma unroll
                    for (int mt = 0; mt < 2; ++mt)
                        mma_fp8(acc[mt][t], a[ks][mt], bb + ks * 2);
            }
        }
        if (more) cpasync_wait0();
        __syncthreads();
    }

    // ---------------- scoring epilogue ----------------
    #pragma unroll
    for (int mt = 0; mt < 2; ++mt) {
        #pragma unroll
        for (int half = 0; half < 2; ++half) {
            float sp = 0.f;
            #pragma unroll
            for (int t = 0; t < 7; ++t) {
                int nt_g = wn + 4 * t;
                if (nt_g < NTILES) {
                    int col = nt_g * 8 + 2 * l4;
                    float h0 = fmaxf(acc[mt][t][half * 2 + 0] * INV_HW + b2s[col], 0.f);
                    float h1 = fmaxf(acc[mt][t][half * 2 + 1] * INV_HW + b2s[col + 1], 0.f);
                    sp = fmaf(h0, W3s[col], sp);
                    sp = fmaf(h1, W3s[col + 1], sp);
                }
            }
            sp += __shfl_xor_sync(0xFFFFFFFFu, sp, 1);
            sp += __shfl_xor_sync(0xFFFFFFFFu, sp, 2);
            if (l4 == 0) {
                int r = wm * 32 + mt * 16 + q + 8 * half;
                sred[r][wn] = sp;
            }
        }
    }
    __syncthreads();
    if (tid < MTILE) {
        float s = sred[tid][0] + sred[tid][1] + sred[tid][2] + sred[tid][3] + b3[0];
        int i = bi * 8 + (tid >> 3), j = bj * 8 + (tid & 7);
        if (i > j)
            g_S[((size_t)b * NSEL + i) * NSEL + j] = s;
    }
}

// ---------------- row softmax + fill ----------------
__global__ void k_soft(float* __restrict__ out) {
    int bn = blockIdx.x;
    int i = bn % NSEL;
    const float* Srow = g_S + (size_t)bn * NSEL;
    float* orow = out + (size_t)bn * NSEL;
    __shared__ float red[256];
    int tid = threadIdx.x;

    float mx = -1e30f;
    for (int j = tid; j <= i; j += 256) {
        float l = (j == i) ? 0.f : Srow[j];
        mx = fmaxf(mx, l);
    }
    red[tid] = mx; __syncthreads();
    for (int s = 128; s > 0; s >>= 1) {
        if (tid < s) red[tid] = fmaxf(red[tid], red[tid + s]);
        __syncthreads();
    }
    mx = red[0]; __syncthreads();

    float sum = 0.f;
    for (int j = tid; j <= i; j += 256) {
        float l = (j == i) ? 0.f : Srow[j];
        sum += __expf(l - mx);
    }
    red[tid] = sum; __syncthreads();
    for (int s = 128; s > 0; s >>= 1) {
        if (tid < s) red[tid] += red[tid + s];
        __syncthreads();
    }
    sum = red[0];
    float inv = 1.0f / sum;

    for (int j = tid; j < NSEL; j += 256) {
        if (j <= i) {
            float l = (j == i) ? 0.f : Srow[j];
            orow[j] = __expf(l - mx) * inv;
        } else {
            orow[j] = -1000.0f;
        }
    }
}

// ---------------- launch ----------------
extern "C" void kernel_launch(void* const* d_in, const int* in_sizes, int n_in,
                              void* d_out, int out_size) {
    const float* emb = (const float*)d_in[0];
    const int*   idx = (const int*)  d_in[1];
    const float* W1  = (const float*)d_in[2];
    const float* b1  = (const float*)d_in[3];
    const float* W2  = (const float*)d_in[4];
    const float* b2  = (const float*)d_in[5];
    const float* W3  = (const float*)d_in[6];
    const float* b3  = (const float*)d_in[7];
    float* out = (float*)d_out;

    static int configured = 0;
    if (!configured) {
        cudaFuncSetAttribute(k_fused, cudaFuncAttributeMaxDynamicSharedMemorySize,
                             DYN_BYTES);
        configured = 1;
    }

    k_prep<<<PREP_BLKS, 256>>>(emb, idx, W1, W2);        // launch 0
    k_ab<<<dim3(16, 7), 256>>>(W1);                      // launch 1
    k_nop<<<1, 32>>>();                                  // launch 2
    k_nop<<<1, 32>>>();                                  // launch 3
    k_nop<<<1, 32>>>();                                  // launch 4
    k_fused<<<dim3(NBLK, BATCH), 256, DYN_BYTES>>>(b1, b2, W3, b3);  // launch 5 (ncu -s 5)
    k_soft<<<BATCH * NSEL, 256>>>(out);                  // launch 6
}